// round 15
// baseline (speedup 1.0000x reference)
#include <cuda_runtime.h>
#include <cuda_bf16.h>
#include <cuda_fp16.h>
#include <cstdint>

// Problem constants
constexpr int Bn = 4, Tn = 256, Sn = 128, Fn = 256, Hn = 512, Vn = 1024;

// Scratch (allocation-free rule: __device__ globals)
__device__ float g_P[Bn * Tn * Hn];       // [b*T+t][h], includes b1
__device__ float g_Q[Bn * Sn * Hn];       // [b*S+s][h]
// W2 bf16 fragment order: [ck(16)][ntile(8)] x 512 uint4
__device__ uint4 g_W2f[16 * 8 * 512];
// A bf16 fragment order: [bt(1024)][ck(16)] x 512 uint4  (128 MB)
__device__ uint4 g_Af[(size_t)1024 * 16 * 512];
// fp16 raw logits scratch (256 MB)
__device__ __half g_L[(size_t)Bn * Tn * Sn * Vn];

// ---------------------------------------------------------------------------
// helpers
// ---------------------------------------------------------------------------
__device__ __forceinline__ uint32_t packbf(float lo, float hi) {
    __nv_bfloat162 h = __floats2bfloat162_rn(lo, hi);   // lo -> low 16 bits
    return *reinterpret_cast<uint32_t*>(&h);
}

__device__ __forceinline__ uint32_t smem_u32(const void* p) {
    uint32_t a;
    asm("{ .reg .u64 t; cvta.to.shared.u64 t, %1; cvt.u32.u64 %0, t; }"
        : "=r"(a) : "l"(p));
    return a;
}

__device__ __forceinline__ void cp16(uint32_t smem_dst, const void* gmem_src) {
    asm volatile("cp.async.cg.shared.global [%0], [%1], 16;"
                 :: "r"(smem_dst), "l"(gmem_src));
}
__device__ __forceinline__ void cp_commit() {
    asm volatile("cp.async.commit_group;");
}
template <int N>
__device__ __forceinline__ void cp_wait() {
    asm volatile("cp.async.wait_group %0;" :: "n"(N));
}

__device__ __forceinline__ void mma_bf16(float (&c)[4], const uint32_t (&a)[4],
                                         uint32_t b0, uint32_t b1) {
    asm volatile(
        "mma.sync.aligned.m16n8k16.row.col.f32.bf16.bf16.f32 "
        "{%0,%1,%2,%3}, {%4,%5,%6,%7}, {%8,%9}, {%0,%1,%2,%3};"
        : "+f"(c[0]), "+f"(c[1]), "+f"(c[2]), "+f"(c[3])
        : "r"(a[0]), "r"(a[1]), "r"(a[2]), "r"(a[3]), "r"(b0), "r"(b1));
}

// ---------------------------------------------------------------------------
// W2 [H][V] f32 -> g_W2f bf16 fragment order (one-time, 1MB out).
// ---------------------------------------------------------------------------
__global__ void w2frag_kernel(const float* __restrict__ W2) {
    const int n  = blockIdx.x * 256 + threadIdx.x;   // 0..1023
    const int ck = blockIdx.y;                       // 0..15 (32-K chunk)
    const int nt = n >> 7, wn = (n >> 6) & 1, j = (n >> 3) & 7, g = n & 7;
#pragma unroll
    for (int q = 0; q < 4; q++) {
        uint4 v;
        int k0 = ck * 32 + 2 * q;
        v.x = packbf(W2[(size_t)k0 * Vn + n],        W2[(size_t)(k0 + 1) * Vn + n]);
        v.y = packbf(W2[(size_t)(k0 + 8) * Vn + n],  W2[(size_t)(k0 + 9) * Vn + n]);
        v.z = packbf(W2[(size_t)(k0 + 16) * Vn + n], W2[(size_t)(k0 + 17) * Vn + n]);
        v.w = packbf(W2[(size_t)(k0 + 24) * Vn + n], W2[(size_t)(k0 + 25) * Vn + n]);
        g_W2f[(size_t)(ck * 8 + nt) * 512 + (wn * 8 + j) * 32 + 4 * g + q] = v;
    }
}

// ---------------------------------------------------------------------------
// Layer-1 projection, split over (row-tile 8, h-tile 128): 768 blocks.
// ---------------------------------------------------------------------------
__global__ __launch_bounds__(256)
void proj_kernel(const float* __restrict__ src, const float* __restrict__ tgt,
                 const float* __restrict__ W1, const float* __restrict__ b1) {
    __shared__ float se[8][Fn];
    const int rt = blockIdx.x;
    const bool isP = rt < 128;
    const float* enc = isP ? src : tgt;
    float* dst = isP ? g_P : g_Q;
    const float* Wp = isP ? W1 : (W1 + Fn * Hn);
    const int row0 = (isP ? rt : rt - 128) * 8;

    const int tid = threadIdx.x;
    for (int i = tid; i < 8 * Fn; i += 256)
        se[i >> 8][i & 255] = enc[(size_t)row0 * Fn + i];
    __syncthreads();

    const int h  = blockIdx.y * 128 + (tid & 127);
    const int rh = tid >> 7;               // 0..1 -> 4-row half

    float acc[4] = {0.f, 0.f, 0.f, 0.f};
    const float* w = Wp + h;
    for (int f = 0; f < Fn; f++) {
        float wv = w[(size_t)f * Hn];
#pragma unroll
        for (int r = 0; r < 4; r++)
            acc[r] = fmaf(se[rh * 4 + r][f], wv, acc[r]);
    }
    const float bias = isP ? b1[h] : 0.f;
#pragma unroll
    for (int r = 0; r < 4; r++)
        dst[(size_t)(row0 + rh * 4 + r) * Hn + h] = acc[r] + bias;
}

// ---------------------------------------------------------------------------
// A-fragment materializer: for each bt, write relu(P[bt]+Q[b]) as bf16
// m16n8k16 A row-major fragments. One block per bt, 16 K-chunks.
// ---------------------------------------------------------------------------
__global__ __launch_bounds__(256)
void afrag_kernel() {
    __shared__ float sP[Hn];
    const int bt  = blockIdx.x;
    const int b   = bt >> 8;
    const int tid = threadIdx.x;

    if (tid < 128)
        ((float4*)sP)[tid] = *((const float4*)(g_P + (size_t)bt * Hn) + tid);
    __syncthreads();

    // decode: tid = wm[7:6] i[5] g[4:2] kki[1] qh[0]
    const int wm = tid >> 6, ii = (tid >> 5) & 1;
    const int g = (tid >> 2) & 7, kki = (tid >> 1) & 1, qh = tid & 1;
    const int mtile = wm * 2 + ii;
    const int entry = mtile * 2 + kki;
    const int lt = 4 * g + 2 * qh;            // fragment lanes lt, lt+1
    const int s_lo = mtile * 16 + g;
    const int ka_ = kki * 16 + qh * 4;        // k offset within 32-chunk
    const float* qlo = g_Q + (size_t)b * Sn * Hn + (size_t)s_lo * Hn + ka_;
    const float* qhi = qlo + 8 * Hn;
    uint4* dst = g_Af + (size_t)bt * 8192 + entry * 32;

    float4 qv0 = *(const float4*)(qlo);
    float4 qv1 = *(const float4*)(qlo + 8);
    float4 qv2 = *(const float4*)(qhi);
    float4 qv3 = *(const float4*)(qhi + 8);

    for (int ck = 0; ck < 16; ck++) {
        const int k0 = ck * 32;
        float4 pa = *(const float4*)(sP + k0 + ka_);
        float4 pb = *(const float4*)(sP + k0 + ka_ + 8);
        uint4 u0, u1;
        u0.x = packbf(fmaxf(qv0.x + pa.x, 0.f), fmaxf(qv0.y + pa.y, 0.f));
        u0.y = packbf(fmaxf(qv2.x + pa.x, 0.f), fmaxf(qv2.y + pa.y, 0.f));
        u0.z = packbf(fmaxf(qv1.x + pb.x, 0.f), fmaxf(qv1.y + pb.y, 0.f));
        u0.w = packbf(fmaxf(qv3.x + pb.x, 0.f), fmaxf(qv3.y + pb.y, 0.f));
        u1.x = packbf(fmaxf(qv0.z + pa.z, 0.f), fmaxf(qv0.w + pa.w, 0.f));
        u1.y = packbf(fmaxf(qv2.z + pa.z, 0.f), fmaxf(qv2.w + pa.w, 0.f));
        u1.z = packbf(fmaxf(qv1.z + pb.z, 0.f), fmaxf(qv1.w + pb.w, 0.f));
        u1.w = packbf(fmaxf(qv3.z + pb.z, 0.f), fmaxf(qv3.w + pb.w, 0.f));
        if (ck < 15) {                        // prefetch next Q chunk
            qv0 = *(const float4*)(qlo + k0 + 32);
            qv1 = *(const float4*)(qlo + k0 + 40);
            qv2 = *(const float4*)(qhi + k0 + 32);
            qv3 = *(const float4*)(qhi + k0 + 40);
        }
        dst[lt]     = u0;
        dst[lt + 1] = u1;
        dst += 512;                           // next ck
    }
}

// ---------------------------------------------------------------------------
// GEMM body (R12 config): BM=128 BN=128 BK=32 per stage, m16n8k16, 8 warps
// 4x2, 6 stage buffers, one __syncthreads per stage pair, odd stage
// barrier-free (warp skew).
// ---------------------------------------------------------------------------
constexpr uint32_t STAGE_U4 = 1024;           // uint4 per stage (A 512 + B 512)
constexpr uint32_t SMEM_DYN = 6 * STAGE_U4 * 16;   // 98304 B

__device__ __forceinline__ void gemm_body(int bt, int nt) {
    extern __shared__ uint4 sm4[];

    const int tid = threadIdx.x;
    const int wid = tid >> 5;
    const int lane = tid & 31;
    const int wm = wid & 3;                   // 32-row slice
    const int wn = wid >> 2;                  // 64-col slice

    const uint4* Asrc = g_Af + (size_t)bt * 8192;         // +ck*512
    const uint4* Bsrc = g_W2f + (size_t)nt * 512;         // +ck*8*512

    auto fill = [&](int stage, int buf) {
        uint32_t dst = smem_u32(sm4 + buf * STAGE_U4);
        const char* as = (const char*)(Asrc + (size_t)stage * 512);
        const char* bs = (const char*)(Bsrc + (size_t)stage * 8 * 512);
#pragma unroll
        for (int r = 0; r < 2; r++) {
            int c = tid + 256 * r;            // 0..511
            cp16(dst + c * 16, as + c * 16);
            cp16(dst + 8192 + c * 16, bs + c * 16);
        }
    };
    auto issue_pair = [&](int gidx) {
        int buf = 2 * (gidx % 3);
        fill(2 * gidx, buf);
        fill(2 * gidx + 1, buf + 1);
        cp_commit();
    };

    issue_pair(0);
    issue_pair(1);

    float acc[2][8][4];
#pragma unroll
    for (int i = 0; i < 2; i++)
#pragma unroll
        for (int j = 0; j < 8; j++)
#pragma unroll
            for (int e = 0; e < 4; e++) acc[i][j][e] = 0.f;

    auto do_stage = [&](int buf) {
        const uint4* Ab = sm4 + buf * STAGE_U4;
        const uint4* Bb = Ab + 512 + (wn * 8) * 32;

        uint32_t a00[4], a01[4], a10[4], a11[4];
        *(uint4*)a00 = Ab[((wm * 2 + 0) * 2 + 0) * 32 + lane];
        *(uint4*)a01 = Ab[((wm * 2 + 0) * 2 + 1) * 32 + lane];
        *(uint4*)a10 = Ab[((wm * 2 + 1) * 2 + 0) * 32 + lane];
        *(uint4*)a11 = Ab[((wm * 2 + 1) * 2 + 1) * 32 + lane];

#pragma unroll
        for (int j = 0; j < 8; j++) {
            uint4 bv = Bb[j * 32 + lane];
            mma_bf16(acc[0][j], a00, bv.x, bv.y);
            mma_bf16(acc[0][j], a01, bv.z, bv.w);
            mma_bf16(acc[1][j], a10, bv.x, bv.y);
            mma_bf16(acc[1][j], a11, bv.z, bv.w);
        }
    };

    for (int k = 0; k < 8; k++) {
        if (k < 7) cp_wait<1>();              // group k complete
        else       cp_wait<0>();
        __syncthreads();                      // all warps enter step k

        const int bufe = 2 * (k % 3);
        do_stage(bufe);                       // stage 2k

        if (k < 6) issue_pair(k + 2);         // writes group k-1's buffers (dead)

        do_stage(bufe + 1);                   // stage 2k+1 (no wait, no barrier)
    }

    // epilogue: fp16 raw logits to g_L (streaming stores)
    const int gg = lane >> 2, tq = lane & 3;
    const size_t rowbase = (size_t)bt * Sn;
#pragma unroll
    for (int i = 0; i < 2; i++) {
        int r0 = wm * 32 + i * 16 + gg;
#pragma unroll
        for (int j = 0; j < 8; j++) {
            int col = nt * 128 + wn * 64 + 8 * j + 2 * tq;
            __half2 v0 = __floats2half2_rn(acc[i][j][0], acc[i][j][1]);
            __half2 v1 = __floats2half2_rn(acc[i][j][2], acc[i][j][3]);
            __stcs((__half2*)(g_L + (rowbase + r0) * Vn + col), v0);
            __stcs((__half2*)(g_L + (rowbase + r0 + 8) * Vn + col), v1);
        }
    }
}

// ---------------------------------------------------------------------------
// log_softmax body: one warp per row, 8 rows per block (row = rbase + wid).
// ---------------------------------------------------------------------------
__device__ __forceinline__ void lsm_body(float* __restrict__ out,
                                         const float* __restrict__ b2,
                                         int rbase) {
    const int row  = rbase + (threadIdx.x >> 5);
    const int lane = threadIdx.x & 31;

    const uint4* pL = (const uint4*)(g_L + (size_t)row * Vn);  // 8 halves each
    const float4* pb = (const float4*)b2;

    float v[32];
    float mx = -1e30f;
#pragma unroll
    for (int i = 0; i < 4; i++) {
        uint4 u = __ldcs(&pL[lane + 32 * i]);
        int c4 = (lane + 32 * i) * 2;          // float4 index into b2
        float4 b0 = __ldg(&pb[c4]);
        float4 b1 = __ldg(&pb[c4 + 1]);
        float2 f0 = __half22float2(*(__half2*)&u.x);
        float2 f1 = __half22float2(*(__half2*)&u.y);
        float2 f2 = __half22float2(*(__half2*)&u.z);
        float2 f3 = __half22float2(*(__half2*)&u.w);
        float* vv = v + 8 * i;
        vv[0] = f0.x + b0.x; vv[1] = f0.y + b0.y;
        vv[2] = f1.x + b0.z; vv[3] = f1.y + b0.w;
        vv[4] = f2.x + b1.x; vv[5] = f2.y + b1.y;
        vv[6] = f3.x + b1.z; vv[7] = f3.y + b1.w;
#pragma unroll
        for (int e = 0; e < 8; e++) mx = fmaxf(mx, vv[e]);
    }
#pragma unroll
    for (int o = 16; o > 0; o >>= 1)
        mx = fmaxf(mx, __shfl_xor_sync(0xffffffffu, mx, o));

    float sum = 0.f;
#pragma unroll
    for (int e = 0; e < 32; e++) sum += __expf(v[e] - mx);
#pragma unroll
    for (int o = 16; o > 0; o >>= 1)
        sum += __shfl_xor_sync(0xffffffffu, sum, o);

    const float lse = mx + logf(sum);
    float4* po = (float4*)(out + (size_t)row * Vn);
#pragma unroll
    for (int i = 0; i < 4; i++) {
        const float* vv = v + 8 * i;
        __stcs(&po[(lane + 32 * i) * 2],
               make_float4(vv[0] - lse, vv[1] - lse, vv[2] - lse, vv[3] - lse));
        __stcs(&po[(lane + 32 * i) * 2 + 1],
               make_float4(vv[4] - lse, vv[5] - lse, vv[6] - lse, vv[7] - lse));
    }
}

// ---------------------------------------------------------------------------
// Standalone kernels + mixed combo kernel (single stream, no events).
// combo grid = 6144: bid%3==0 -> gemm block (2048), else lsm block (4096).
// gemm(c) and lsm(c-1) are independent; lsm(c-1)'s inputs were written by
// the PREVIOUS launch (stream order guarantees visibility).
// ---------------------------------------------------------------------------
__global__ __launch_bounds__(256, 2)
void joint_gemm(int bt0) {
    gemm_body(bt0 + (blockIdx.x >> 3), blockIdx.x & 7);
}

__global__ __launch_bounds__(256)
void lsm_kernel(float* __restrict__ out, const float* __restrict__ b2,
                int row0) {
    lsm_body(out, b2, row0 + blockIdx.x * 8);
}

__global__ __launch_bounds__(256, 2)
void combo_kernel(int bt0, int row0, float* __restrict__ out,
                  const float* __restrict__ b2) {
    const int bid = blockIdx.x;
    if (bid % 3 == 0) {
        const int v = bid / 3;                // 0..2047
        gemm_body(bt0 + (v >> 3), v & 7);
    } else {
        const int u = (bid / 3) * 2 + (bid % 3) - 1;   // 0..4095
        lsm_body(out, b2, row0 + u * 8);
    }
}

// ---------------------------------------------------------------------------
extern "C" void kernel_launch(void* const* d_in, const int* in_sizes, int n_in,
                              void* d_out, int out_size) {
    const float* src = (const float*)d_in[0];  // [B,T,F]
    const float* tgt = (const float*)d_in[1];  // [B,S,F]
    const float* W1  = (const float*)d_in[2];  // [2F,H]
    const float* b1  = (const float*)d_in[3];  // [H]
    const float* W2  = (const float*)d_in[4];  // [H,V]
    const float* b2  = (const float*)d_in[5];  // [V]
    float* out = (float*)d_out;                // [B,T,S,V]

    (void)in_sizes; (void)n_in; (void)out_size;

    constexpr int NCHUNK = 4;
    constexpr int BT_PER = (Bn * Tn) / NCHUNK;           // 256 bt per chunk
    constexpr int ROWS_PER = BT_PER * Sn;                // 32768 rows per chunk

    cudaFuncSetAttribute(joint_gemm,
                         cudaFuncAttributeMaxDynamicSharedMemorySize, SMEM_DYN);
    cudaFuncSetAttribute(combo_kernel,
                         cudaFuncAttributeMaxDynamicSharedMemorySize, SMEM_DYN);

    // prep
    w2frag_kernel<<<dim3(4, 16), 256>>>(W2);
    proj_kernel<<<dim3(192, 4), 256>>>(src, tgt, W1, b1);
    afrag_kernel<<<1024, 256>>>();

    // chunk 0: pure gemm
    joint_gemm<<<8 * BT_PER, 256, SMEM_DYN>>>(0);
    // chunks 1..3: gemm(c) + lsm(c-1) interleaved in one grid
    for (int c = 1; c < NCHUNK; c++)
        combo_kernel<<<6144, 256, SMEM_DYN>>>(c * BT_PER, (c - 1) * ROWS_PER,
                                              out, b2);
    // final: pure lsm for chunk 3
    lsm_kernel<<<ROWS_PER / 8, 256>>>(out, b2, (NCHUNK - 1) * ROWS_PER);
}

// round 16
// speedup vs baseline: 1.1533x; 1.1533x over previous
#include <cuda_runtime.h>
#include <cuda_bf16.h>
#include <cuda_fp16.h>
#include <cstdint>

// Problem constants
constexpr int Bn = 4, Tn = 256, Sn = 128, Fn = 256, Hn = 512, Vn = 1024;

// Scratch (allocation-free rule: __device__ globals)
__device__ float g_P[Bn * Tn * Hn];       // [b*T+t][h], includes b1
__device__ float g_Q[Bn * Sn * Hn];       // [b*S+s][h]
// W2 bf16 fragment order: [ck(16)][ntile(8)] x 512 uint4
__device__ uint4 g_W2f[16 * 8 * 512];
// A bf16 fragment order: [bt(1024)][ck(16)] x 512 uint4  (128 MB)
__device__ uint4 g_Af[(size_t)1024 * 16 * 512];
// fp16 raw logits scratch (256 MB)
__device__ __half g_L[(size_t)Bn * Tn * Sn * Vn];

// ---------------------------------------------------------------------------
// helpers
// ---------------------------------------------------------------------------
__device__ __forceinline__ uint32_t packbf(float lo, float hi) {
    __nv_bfloat162 h = __floats2bfloat162_rn(lo, hi);   // lo -> low 16 bits
    return *reinterpret_cast<uint32_t*>(&h);
}

__device__ __forceinline__ uint32_t smem_u32(const void* p) {
    uint32_t a;
    asm("{ .reg .u64 t; cvta.to.shared.u64 t, %1; cvt.u32.u64 %0, t; }"
        : "=r"(a) : "l"(p));
    return a;
}

__device__ __forceinline__ void cp16(uint32_t smem_dst, const void* gmem_src) {
    asm volatile("cp.async.cg.shared.global [%0], [%1], 16;"
                 :: "r"(smem_dst), "l"(gmem_src));
}
__device__ __forceinline__ void cp_commit() {
    asm volatile("cp.async.commit_group;");
}
template <int N>
__device__ __forceinline__ void cp_wait() {
    asm volatile("cp.async.wait_group %0;" :: "n"(N));
}

__device__ __forceinline__ void mma_bf16(float (&c)[4], const uint32_t (&a)[4],
                                         uint32_t b0, uint32_t b1) {
    asm volatile(
        "mma.sync.aligned.m16n8k16.row.col.f32.bf16.bf16.f32 "
        "{%0,%1,%2,%3}, {%4,%5,%6,%7}, {%8,%9}, {%0,%1,%2,%3};"
        : "+f"(c[0]), "+f"(c[1]), "+f"(c[2]), "+f"(c[3])
        : "r"(a[0]), "r"(a[1]), "r"(a[2]), "r"(a[3]), "r"(b0), "r"(b1));
}

// ---------------------------------------------------------------------------
// W2 [H][V] f32 -> g_W2f bf16 fragment order (one-time, 1MB out).
// ---------------------------------------------------------------------------
__global__ void w2frag_kernel(const float* __restrict__ W2) {
    const int n  = blockIdx.x * 256 + threadIdx.x;   // 0..1023
    const int ck = blockIdx.y;                       // 0..15 (32-K chunk)
    const int nt = n >> 7, wn = (n >> 6) & 1, j = (n >> 3) & 7, g = n & 7;
#pragma unroll
    for (int q = 0; q < 4; q++) {
        uint4 v;
        int k0 = ck * 32 + 2 * q;
        v.x = packbf(W2[(size_t)k0 * Vn + n],        W2[(size_t)(k0 + 1) * Vn + n]);
        v.y = packbf(W2[(size_t)(k0 + 8) * Vn + n],  W2[(size_t)(k0 + 9) * Vn + n]);
        v.z = packbf(W2[(size_t)(k0 + 16) * Vn + n], W2[(size_t)(k0 + 17) * Vn + n]);
        v.w = packbf(W2[(size_t)(k0 + 24) * Vn + n], W2[(size_t)(k0 + 25) * Vn + n]);
        g_W2f[(size_t)(ck * 8 + nt) * 512 + (wn * 8 + j) * 32 + 4 * g + q] = v;
    }
}

// ---------------------------------------------------------------------------
// Layer-1 projection, split over (row-tile 8, h-tile 128): 768 blocks.
// ---------------------------------------------------------------------------
__global__ __launch_bounds__(256)
void proj_kernel(const float* __restrict__ src, const float* __restrict__ tgt,
                 const float* __restrict__ W1, const float* __restrict__ b1) {
    __shared__ float se[8][Fn];
    const int rt = blockIdx.x;
    const bool isP = rt < 128;
    const float* enc = isP ? src : tgt;
    float* dst = isP ? g_P : g_Q;
    const float* Wp = isP ? W1 : (W1 + Fn * Hn);
    const int row0 = (isP ? rt : rt - 128) * 8;

    const int tid = threadIdx.x;
    for (int i = tid; i < 8 * Fn; i += 256)
        se[i >> 8][i & 255] = enc[(size_t)row0 * Fn + i];
    __syncthreads();

    const int h  = blockIdx.y * 128 + (tid & 127);
    const int rh = tid >> 7;               // 0..1 -> 4-row half

    float acc[4] = {0.f, 0.f, 0.f, 0.f};
    const float* w = Wp + h;
    for (int f = 0; f < Fn; f++) {
        float wv = w[(size_t)f * Hn];
#pragma unroll
        for (int r = 0; r < 4; r++)
            acc[r] = fmaf(se[rh * 4 + r][f], wv, acc[r]);
    }
    const float bias = isP ? b1[h] : 0.f;
#pragma unroll
    for (int r = 0; r < 4; r++)
        dst[(size_t)(row0 + rh * 4 + r) * Hn + h] = acc[r] + bias;
}

// ---------------------------------------------------------------------------
// A-fragment materializer with 4-way t-batching: one block handles 4
// consecutive bt (same b). Q chunk is loaded into registers ONCE and reused
// against 4 P rows (smem) -> Q L2 traffic drops 4x vs one-bt-per-block.
// Output layout identical to before: [bt][ck(16)] x 512 uint4.
// ---------------------------------------------------------------------------
__global__ __launch_bounds__(256)
void afrag_kernel() {
    __shared__ float sP[4][Hn];               // 4 P rows, 8 KB
    const int bt0 = blockIdx.x * 4;           // 4 bt share one b (256 | 4)
    const int b   = bt0 >> 8;
    const int tid = threadIdx.x;

#pragma unroll
    for (int r = 0; r < 2; r++) {
        int i4 = tid + 256 * r;               // 0..511 float4s
        int tt = i4 >> 7, h4 = i4 & 127;
        ((float4*)sP[tt])[h4] =
            ((const float4*)(g_P + (size_t)(bt0 + tt) * Hn))[h4];
    }
    __syncthreads();

    // decode: tid = wm[7:6] i[5] g[4:2] kki[1] qh[0]
    const int wm = tid >> 6, ii = (tid >> 5) & 1;
    const int g = (tid >> 2) & 7, kki = (tid >> 1) & 1, qh = tid & 1;
    const int mtile = wm * 2 + ii;
    const int entry = mtile * 2 + kki;
    const int lt = 4 * g + 2 * qh;            // fragment lanes lt, lt+1
    const int s_lo = mtile * 16 + g;
    const int ka_ = kki * 16 + qh * 4;        // k offset within 32-chunk
    const float* qlo = g_Q + (size_t)b * Sn * Hn + (size_t)s_lo * Hn + ka_;
    const float* qhi = qlo + 8 * Hn;

    float4 qv0 = *(const float4*)(qlo);
    float4 qv1 = *(const float4*)(qlo + 8);
    float4 qv2 = *(const float4*)(qhi);
    float4 qv3 = *(const float4*)(qhi + 8);

    for (int ck = 0; ck < 16; ck++) {
        const int k0 = ck * 32;
#pragma unroll
        for (int tt = 0; tt < 4; tt++) {
            float4 pa = *(const float4*)(sP[tt] + k0 + ka_);
            float4 pb = *(const float4*)(sP[tt] + k0 + ka_ + 8);
            uint4 u0, u1;
            u0.x = packbf(fmaxf(qv0.x + pa.x, 0.f), fmaxf(qv0.y + pa.y, 0.f));
            u0.y = packbf(fmaxf(qv2.x + pa.x, 0.f), fmaxf(qv2.y + pa.y, 0.f));
            u0.z = packbf(fmaxf(qv1.x + pb.x, 0.f), fmaxf(qv1.y + pb.y, 0.f));
            u0.w = packbf(fmaxf(qv3.x + pb.x, 0.f), fmaxf(qv3.y + pb.y, 0.f));
            u1.x = packbf(fmaxf(qv0.z + pa.z, 0.f), fmaxf(qv0.w + pa.w, 0.f));
            u1.y = packbf(fmaxf(qv2.z + pa.z, 0.f), fmaxf(qv2.w + pa.w, 0.f));
            u1.z = packbf(fmaxf(qv1.z + pb.z, 0.f), fmaxf(qv1.w + pb.w, 0.f));
            u1.w = packbf(fmaxf(qv3.z + pb.z, 0.f), fmaxf(qv3.w + pb.w, 0.f));
            uint4* dst = g_Af + (size_t)(bt0 + tt) * 8192 + ck * 512 + entry * 32;
            dst[lt]     = u0;
            dst[lt + 1] = u1;
        }
        if (ck < 15) {                        // prefetch next Q chunk
            qv0 = *(const float4*)(qlo + k0 + 32);
            qv1 = *(const float4*)(qlo + k0 + 40);
            qv2 = *(const float4*)(qhi + k0 + 32);
            qv3 = *(const float4*)(qhi + k0 + 40);
        }
    }
}

// ---------------------------------------------------------------------------
// Main GEMM (R12 config): BM=128 BN=128 BK=32 per stage, m16n8k16, 8 warps
// 4x2, 6 stage buffers, one __syncthreads per stage pair, odd stage
// barrier-free (warp skew).
// ---------------------------------------------------------------------------
constexpr uint32_t STAGE_U4 = 1024;           // uint4 per stage (A 512 + B 512)
constexpr uint32_t SMEM_DYN = 6 * STAGE_U4 * 16;   // 98304 B

__global__ __launch_bounds__(256, 2)
void joint_gemm() {
    extern __shared__ uint4 sm4[];

    const int bt  = blockIdx.y;               // b*T + t
    const int nt  = blockIdx.x;               // n-tile, n0 = nt*128
    const int tid = threadIdx.x;
    const int wid = tid >> 5;
    const int lane = tid & 31;
    const int wm = wid & 3;                   // 32-row slice
    const int wn = wid >> 2;                  // 64-col slice

    const uint4* Asrc = g_Af + (size_t)bt * 8192;         // +ck*512
    const uint4* Bsrc = g_W2f + (size_t)nt * 512;         // +ck*8*512

    // fill ONE stage buffer (no commit)
    auto fill = [&](int stage, int buf) {
        uint32_t dst = smem_u32(sm4 + buf * STAGE_U4);
        const char* as = (const char*)(Asrc + (size_t)stage * 512);
        const char* bs = (const char*)(Bsrc + (size_t)stage * 8 * 512);
#pragma unroll
        for (int r = 0; r < 2; r++) {
            int c = tid + 256 * r;            // 0..511
            cp16(dst + c * 16, as + c * 16);
            cp16(dst + 8192 + c * 16, bs + c * 16);
        }
    };
    // group g covers stages 2g, 2g+1 -> buffers 2*(g%3), 2*(g%3)+1
    auto issue_pair = [&](int gidx) {
        int buf = 2 * (gidx % 3);
        fill(2 * gidx, buf);
        fill(2 * gidx + 1, buf + 1);
        cp_commit();
    };

    issue_pair(0);
    issue_pair(1);

    float acc[2][8][4];
#pragma unroll
    for (int i = 0; i < 2; i++)
#pragma unroll
        for (int j = 0; j < 8; j++)
#pragma unroll
            for (int e = 0; e < 4; e++) acc[i][j][e] = 0.f;

    // MMA for one resident stage buffer
    auto do_stage = [&](int buf) {
        const uint4* Ab = sm4 + buf * STAGE_U4;
        const uint4* Bb = Ab + 512 + (wn * 8) * 32;

        uint32_t a00[4], a01[4], a10[4], a11[4];
        *(uint4*)a00 = Ab[((wm * 2 + 0) * 2 + 0) * 32 + lane];
        *(uint4*)a01 = Ab[((wm * 2 + 0) * 2 + 1) * 32 + lane];
        *(uint4*)a10 = Ab[((wm * 2 + 1) * 2 + 0) * 32 + lane];
        *(uint4*)a11 = Ab[((wm * 2 + 1) * 2 + 1) * 32 + lane];

#pragma unroll
        for (int j = 0; j < 8; j++) {
            uint4 bv = Bb[j * 32 + lane];
            mma_bf16(acc[0][j], a00, bv.x, bv.y);
            mma_bf16(acc[0][j], a01, bv.z, bv.w);
            mma_bf16(acc[1][j], a10, bv.x, bv.y);
            mma_bf16(acc[1][j], a11, bv.z, bv.w);
        }
    };

    for (int k = 0; k < 8; k++) {
        if (k < 7) cp_wait<1>();              // group k complete
        else       cp_wait<0>();
        __syncthreads();                      // all warps enter step k

        const int bufe = 2 * (k % 3);
        do_stage(bufe);                       // stage 2k

        if (k < 6) issue_pair(k + 2);         // writes group k-1's buffers (dead)

        do_stage(bufe + 1);                   // stage 2k+1 (no wait, no barrier)
    }

    // ---- epilogue: fp16 raw logits to g_L (streaming stores) ----
    const int gg = lane >> 2, tq = lane & 3;
    const size_t rowbase = (size_t)bt * Sn;
#pragma unroll
    for (int i = 0; i < 2; i++) {
        int r0 = wm * 32 + i * 16 + gg;
#pragma unroll
        for (int j = 0; j < 8; j++) {
            int col = nt * 128 + wn * 64 + 8 * j + 2 * tq;
            __half2 v0 = __floats2half2_rn(acc[i][j][0], acc[i][j][1]);
            __half2 v1 = __floats2half2_rn(acc[i][j][2], acc[i][j][3]);
            __stcs((__half2*)(g_L + (rowbase + r0) * Vn + col), v0);
            __stcs((__half2*)(g_L + (rowbase + r0 + 8) * Vn + col), v1);
        }
    }
}

// ---------------------------------------------------------------------------
// log_softmax: read fp16 logits from g_L (streaming), add b2, write fp32 out.
// One warp per row; 32 values per lane.
// ---------------------------------------------------------------------------
__global__ __launch_bounds__(256)
void lsm_kernel(float* __restrict__ out, const float* __restrict__ b2) {
    const int row  = blockIdx.x * 8 + (threadIdx.x >> 5);
    const int lane = threadIdx.x & 31;

    const uint4* pL = (const uint4*)(g_L + (size_t)row * Vn);  // 8 halves each
    const float4* pb = (const float4*)b2;

    float v[32];
    float mx = -1e30f;
#pragma unroll
    for (int i = 0; i < 4; i++) {
        uint4 u = __ldcs(&pL[lane + 32 * i]);
        int c4 = (lane + 32 * i) * 2;          // float4 index into b2
        float4 b0 = __ldg(&pb[c4]);
        float4 b1 = __ldg(&pb[c4 + 1]);
        float2 f0 = __half22float2(*(__half2*)&u.x);
        float2 f1 = __half22float2(*(__half2*)&u.y);
        float2 f2 = __half22float2(*(__half2*)&u.z);
        float2 f3 = __half22float2(*(__half2*)&u.w);
        float* vv = v + 8 * i;
        vv[0] = f0.x + b0.x; vv[1] = f0.y + b0.y;
        vv[2] = f1.x + b0.z; vv[3] = f1.y + b0.w;
        vv[4] = f2.x + b1.x; vv[5] = f2.y + b1.y;
        vv[6] = f3.x + b1.z; vv[7] = f3.y + b1.w;
#pragma unroll
        for (int e = 0; e < 8; e++) mx = fmaxf(mx, vv[e]);
    }
#pragma unroll
    for (int o = 16; o > 0; o >>= 1)
        mx = fmaxf(mx, __shfl_xor_sync(0xffffffffu, mx, o));

    float sum = 0.f;
#pragma unroll
    for (int e = 0; e < 32; e++) sum += __expf(v[e] - mx);
#pragma unroll
    for (int o = 16; o > 0; o >>= 1)
        sum += __shfl_xor_sync(0xffffffffu, sum, o);

    const float lse = mx + logf(sum);
    float4* po = (float4*)(out + (size_t)row * Vn);
#pragma unroll
    for (int i = 0; i < 4; i++) {
        const float* vv = v + 8 * i;
        __stcs(&po[(lane + 32 * i) * 2],
               make_float4(vv[0] - lse, vv[1] - lse, vv[2] - lse, vv[3] - lse));
        __stcs(&po[(lane + 32 * i) * 2 + 1],
               make_float4(vv[4] - lse, vv[5] - lse, vv[6] - lse, vv[7] - lse));
    }
}

// ---------------------------------------------------------------------------
extern "C" void kernel_launch(void* const* d_in, const int* in_sizes, int n_in,
                              void* d_out, int out_size) {
    const float* src = (const float*)d_in[0];  // [B,T,F]
    const float* tgt = (const float*)d_in[1];  // [B,S,F]
    const float* W1  = (const float*)d_in[2];  // [2F,H]
    const float* b1  = (const float*)d_in[3];  // [H]
    const float* W2  = (const float*)d_in[4];  // [H,V]
    const float* b2  = (const float*)d_in[5];  // [V]
    float* out = (float*)d_out;                // [B,T,S,V]

    (void)in_sizes; (void)n_in; (void)out_size;

    cudaFuncSetAttribute(joint_gemm,
                         cudaFuncAttributeMaxDynamicSharedMemorySize, SMEM_DYN);

    w2frag_kernel<<<dim3(4, 16), 256>>>(W2);
    proj_kernel<<<dim3(192, 4), 256>>>(src, tgt, W1, b1);
    afrag_kernel<<<256, 256>>>();

    joint_gemm<<<dim3(Vn / 128, Bn * Tn), 256, SMEM_DYN>>>();

    lsm_kernel<<<(Bn * Tn * Sn) / 8, 256>>>(out, b2);
}